// round 6
// baseline (speedup 1.0000x reference)
#include <cuda_runtime.h>
#include <cuda_bf16.h>

// HeadWise_JSD: out = (0.5/12) * sum p * (log p - log q)   [kl_pm == 0 exactly]
// Streaming reduction over 2 x 201 MB fp32.
// R3-R5: 6.15-6.34 TB/s invariant across occupancy/MLP/wave/launch changes.
// R6 isolates the last untested variable: grid-stride (2.4MB-strided 512B
// segments) -> contiguous per-block chunks (~340KB sequential span per block,
// 4KB-contiguous per iteration) for DRAM row / L2 streaming locality.

static __device__ __forceinline__ float term(float p, float q) {
    int ip = __float_as_int(p);
    int iq = __float_as_int(q);
    float mp = __int_as_float((ip & 0x007fffff) | 0x3f800000); // [1,2)
    float mq = __int_as_float((iq & 0x007fffff) | 0x3f800000);
    float lp = __log2f(mp);            // MUFU.LG2, arg in [1,2): tiny ulp err
    float lq = __log2f(mq);
    int   de = (ip >> 23) - (iq >> 23);    // exact exponent diff (p,q > 0)
    return p * ((lp - lq) + (float)de);    // log2-units; ln2 folded at end
}

static __device__ __forceinline__ float term4(float4 pv, float4 qv) {
    float a = term(pv.x, qv.x) + term(pv.y, qv.y);
    float b = term(pv.z, qv.z) + term(pv.w, qv.w);
    return a + b;
}

#define GRID_BLOCKS 592

__device__ float        g_partials[GRID_BLOCKS];
__device__ unsigned int g_done = 0;   // self-resetting: last block zeroes it

__global__ __launch_bounds__(256, 4) void jsd_reduce_kernel(
    const float4* __restrict__ p4,
    const float4* __restrict__ q4,
    float* __restrict__ out,
    int n4)
{
    // contiguous chunk for this block: [start, end)
    const int G     = gridDim.x;
    const int start = (int)((long long)n4 * blockIdx.x       / G);
    const int end   = (int)((long long)n4 * (blockIdx.x + 1) / G);

    float a0 = 0.0f, a1 = 0.0f, a2 = 0.0f, a3 = 0.0f;

    int i = start + threadIdx.x;
    // 8 front-batched streaming LDG.128.CS per macro-iter; block walks its
    // chunk in 16KB steps, each load-set is 4KB-contiguous per 256 threads.
    for (; i + 768 < end; i += 1024) {
        float4 p0 = __ldcs(p4 + i);
        float4 p1 = __ldcs(p4 + i + 256);
        float4 p2 = __ldcs(p4 + i + 512);
        float4 p3 = __ldcs(p4 + i + 768);
        float4 q0 = __ldcs(q4 + i);
        float4 q1 = __ldcs(q4 + i + 256);
        float4 q2 = __ldcs(q4 + i + 512);
        float4 q3 = __ldcs(q4 + i + 768);
        a0 += term4(p0, q0);
        a1 += term4(p1, q1);
        a2 += term4(p2, q2);
        a3 += term4(p3, q3);
    }
    for (; i < end; i += 256)
        a0 += term4(__ldcs(p4 + i), __ldcs(q4 + i));

    float acc = ((a0 + a1) + (a2 + a3));

    // block reduction -> thread 0
    #pragma unroll
    for (int o = 16; o; o >>= 1)
        acc += __shfl_xor_sync(0xffffffffu, acc, o);

    __shared__ float smem[8];
    __shared__ bool  is_last;
    int lane = threadIdx.x & 31;
    int warp = threadIdx.x >> 5;
    if (lane == 0) smem[warp] = acc;
    __syncthreads();

    if (warp == 0) {
        float v = (lane < 8) ? smem[lane] : 0.0f;
        #pragma unroll
        for (int o = 4; o; o >>= 1)
            v += __shfl_xor_sync(0xffffffffu, v, o);
        if (lane == 0) {
            g_partials[blockIdx.x] = v;
            __threadfence();
            unsigned int t = atomicAdd(&g_done, 1u);
            is_last = (t == gridDim.x - 1);
        }
    }
    __syncthreads();

    // last block reduces the 592 partials and writes the scalar result
    if (is_last) {
        __threadfence();
        float v = 0.0f;
        for (int j = threadIdx.x; j < (int)gridDim.x; j += 256)
            v += g_partials[j];
        #pragma unroll
        for (int o = 16; o; o >>= 1)
            v += __shfl_xor_sync(0xffffffffu, v, o);
        if (lane == 0) smem[warp] = v;
        __syncthreads();
        if (warp == 0) {
            float s = (lane < 8) ? smem[lane] : 0.0f;
            #pragma unroll
            for (int o = 4; o; o >>= 1)
                s += __shfl_xor_sync(0xffffffffu, s, o);
            if (lane == 0) {
                // log2-units -> nats, times 0.5/NUM_HEADS
                out[0] = s * (0.69314718055994531f * 0.5f / 12.0f);
                g_done = 0;                    // reset for next graph replay
            }
        }
    }
}

extern "C" void kernel_launch(void* const* d_in, const int* in_sizes, int n_in,
                              void* d_out, int out_size) {
    const float4* p4 = (const float4*)d_in[0];
    const float4* q4 = (const float4*)d_in[1];
    float* out = (float*)d_out;

    int n  = in_sizes[0];     // 1024*12*4096
    int n4 = n >> 2;          // 12,582,912 float4 pairs

    jsd_reduce_kernel<<<GRID_BLOCKS, 256>>>(p4, q4, out, n4);
}

// round 7
// speedup vs baseline: 1.0238x; 1.0238x over previous
#include <cuda_runtime.h>
#include <cuda_bf16.h>

// HeadWise_JSD: out = (0.5/12) * sum p * (log p - log q)   [kl_pm == 0 exactly]
// Streaming reduction over 2 x 201 MB fp32.
// R3-R5: 6.15-6.34 TB/s invariant across occupancy/MLP/wave/launch changes.
// R6 isolates the last untested variable: grid-stride (2.4MB-strided 512B
// segments) -> contiguous per-block chunks (~340KB sequential span per block,
// 4KB-contiguous per iteration) for DRAM row / L2 streaming locality.

static __device__ __forceinline__ float term(float p, float q) {
    int ip = __float_as_int(p);
    int iq = __float_as_int(q);
    float mp = __int_as_float((ip & 0x007fffff) | 0x3f800000); // [1,2)
    float mq = __int_as_float((iq & 0x007fffff) | 0x3f800000);
    float lp = __log2f(mp);            // MUFU.LG2, arg in [1,2): tiny ulp err
    float lq = __log2f(mq);
    int   de = (ip >> 23) - (iq >> 23);    // exact exponent diff (p,q > 0)
    return p * ((lp - lq) + (float)de);    // log2-units; ln2 folded at end
}

static __device__ __forceinline__ float term4(float4 pv, float4 qv) {
    float a = term(pv.x, qv.x) + term(pv.y, qv.y);
    float b = term(pv.z, qv.z) + term(pv.w, qv.w);
    return a + b;
}

#define GRID_BLOCKS 592

__device__ float        g_partials[GRID_BLOCKS];
__device__ unsigned int g_done = 0;   // self-resetting: last block zeroes it

__global__ __launch_bounds__(256, 4) void jsd_reduce_kernel(
    const float4* __restrict__ p4,
    const float4* __restrict__ q4,
    float* __restrict__ out,
    int n4)
{
    // contiguous chunk for this block: [start, end)
    const int G     = gridDim.x;
    const int start = (int)((long long)n4 * blockIdx.x       / G);
    const int end   = (int)((long long)n4 * (blockIdx.x + 1) / G);

    float a0 = 0.0f, a1 = 0.0f, a2 = 0.0f, a3 = 0.0f;

    int i = start + threadIdx.x;
    // 8 front-batched streaming LDG.128.CS per macro-iter; block walks its
    // chunk in 16KB steps, each load-set is 4KB-contiguous per 256 threads.
    for (; i + 768 < end; i += 1024) {
        float4 p0 = __ldcs(p4 + i);
        float4 p1 = __ldcs(p4 + i + 256);
        float4 p2 = __ldcs(p4 + i + 512);
        float4 p3 = __ldcs(p4 + i + 768);
        float4 q0 = __ldcs(q4 + i);
        float4 q1 = __ldcs(q4 + i + 256);
        float4 q2 = __ldcs(q4 + i + 512);
        float4 q3 = __ldcs(q4 + i + 768);
        a0 += term4(p0, q0);
        a1 += term4(p1, q1);
        a2 += term4(p2, q2);
        a3 += term4(p3, q3);
    }
    for (; i < end; i += 256)
        a0 += term4(__ldcs(p4 + i), __ldcs(q4 + i));

    float acc = ((a0 + a1) + (a2 + a3));

    // block reduction -> thread 0
    #pragma unroll
    for (int o = 16; o; o >>= 1)
        acc += __shfl_xor_sync(0xffffffffu, acc, o);

    __shared__ float smem[8];
    __shared__ bool  is_last;
    int lane = threadIdx.x & 31;
    int warp = threadIdx.x >> 5;
    if (lane == 0) smem[warp] = acc;
    __syncthreads();

    if (warp == 0) {
        float v = (lane < 8) ? smem[lane] : 0.0f;
        #pragma unroll
        for (int o = 4; o; o >>= 1)
            v += __shfl_xor_sync(0xffffffffu, v, o);
        if (lane == 0) {
            g_partials[blockIdx.x] = v;
            __threadfence();
            unsigned int t = atomicAdd(&g_done, 1u);
            is_last = (t == gridDim.x - 1);
        }
    }
    __syncthreads();

    // last block reduces the 592 partials and writes the scalar result
    if (is_last) {
        __threadfence();
        float v = 0.0f;
        for (int j = threadIdx.x; j < (int)gridDim.x; j += 256)
            v += g_partials[j];
        #pragma unroll
        for (int o = 16; o; o >>= 1)
            v += __shfl_xor_sync(0xffffffffu, v, o);
        if (lane == 0) smem[warp] = v;
        __syncthreads();
        if (warp == 0) {
            float s = (lane < 8) ? smem[lane] : 0.0f;
            #pragma unroll
            for (int o = 4; o; o >>= 1)
                s += __shfl_xor_sync(0xffffffffu, s, o);
            if (lane == 0) {
                // log2-units -> nats, times 0.5/NUM_HEADS
                out[0] = s * (0.69314718055994531f * 0.5f / 12.0f);
                g_done = 0;                    // reset for next graph replay
            }
        }
    }
}

extern "C" void kernel_launch(void* const* d_in, const int* in_sizes, int n_in,
                              void* d_out, int out_size) {
    const float4* p4 = (const float4*)d_in[0];
    const float4* q4 = (const float4*)d_in[1];
    float* out = (float*)d_out;

    int n  = in_sizes[0];     // 1024*12*4096
    int n4 = n >> 2;          // 12,582,912 float4 pairs

    jsd_reduce_kernel<<<GRID_BLOCKS, 256>>>(p4, q4, out, n4);
}

// round 8
// speedup vs baseline: 1.0640x; 1.0393x over previous
#include <cuda_runtime.h>
#include <cuda_bf16.h>

// HeadWise_JSD: out = (0.5/12) * sum p * (log p - log q)   [kl_pm == 0 exactly]
// Streaming reduction over 2 x 201 MB fp32.
// R3-R7: bandwidth pins at 6.32-6.34 TB/s once >=160 lines/SM in flight;
// contiguous chunks regressed (72%) -> grid-stride restored. R8 cuts math
// 3x (2 MUFU + FMUL + FFMA per element via p*lg2(p/q)) to stop math bursts
// from starving LSU issue between load batches.

static __device__ __forceinline__ float term(float p, float q) {
    // lg2(p/q) via MUFU.RCP + MUFU.LG2. |abs err| ~2^-22 per op; weighted by
    // sum(p)=12288 vs output ~O(250) -> worst-case ~7e-6 rel. Fine vs 1e-3.
    float r = __fdividef(p, q);        // MUFU.RCP + FMUL (fast path, no fixup)
    return p * __log2f(r);             // MUFU.LG2 + FMUL; ln2 folded at end
}

static __device__ __forceinline__ float term4(float4 pv, float4 qv) {
    float a = term(pv.x, qv.x) + term(pv.y, qv.y);
    float b = term(pv.z, qv.z) + term(pv.w, qv.w);
    return a + b;
}

__global__ void jsd_zero_kernel(float* out) {
    if (threadIdx.x == 0 && blockIdx.x == 0) out[0] = 0.0f;
}

__global__ __launch_bounds__(256, 4) void jsd_reduce_kernel(
    const float4* __restrict__ p4,
    const float4* __restrict__ q4,
    float* __restrict__ out,
    int n4)
{
    const int stride = gridDim.x * 256;
    int i = blockIdx.x * 256 + threadIdx.x;

    float a0 = 0.0f, a1 = 0.0f, a2 = 0.0f, a3 = 0.0f;

    // 8 front-batched streaming LDG.128.CS per macro-iter (deep MLP)
    for (; i + 3 * stride < n4; i += 4 * stride) {
        float4 p0 = __ldcs(p4 + i);
        float4 p1 = __ldcs(p4 + i + stride);
        float4 p2 = __ldcs(p4 + i + 2 * stride);
        float4 p3 = __ldcs(p4 + i + 3 * stride);
        float4 q0 = __ldcs(q4 + i);
        float4 q1 = __ldcs(q4 + i + stride);
        float4 q2 = __ldcs(q4 + i + 2 * stride);
        float4 q3 = __ldcs(q4 + i + 3 * stride);
        a0 += term4(p0, q0);
        a1 += term4(p1, q1);
        a2 += term4(p2, q2);
        a3 += term4(p3, q3);
    }
    for (; i < n4; i += stride)
        a0 += term4(__ldcs(p4 + i), __ldcs(q4 + i));

    // log2-units -> nats
    float acc = ((a0 + a1) + (a2 + a3)) * 0.69314718055994531f;

    #pragma unroll
    for (int o = 16; o; o >>= 1)
        acc += __shfl_xor_sync(0xffffffffu, acc, o);

    __shared__ float smem[8];
    int lane = threadIdx.x & 31;
    int warp = threadIdx.x >> 5;
    if (lane == 0) smem[warp] = acc;
    __syncthreads();

    if (warp == 0) {
        float v = (lane < 8) ? smem[lane] : 0.0f;
        #pragma unroll
        for (int o = 4; o; o >>= 1)
            v += __shfl_xor_sync(0xffffffffu, v, o);
        if (lane == 0)
            atomicAdd(out, v * (0.5f / 12.0f));
    }
}

extern "C" void kernel_launch(void* const* d_in, const int* in_sizes, int n_in,
                              void* d_out, int out_size) {
    const float4* p4 = (const float4*)d_in[0];
    const float4* q4 = (const float4*)d_in[1];
    float* out = (float*)d_out;

    int n  = in_sizes[0];     // 1024*12*4096
    int n4 = n >> 2;          // 12,582,912 float4 pairs

    jsd_zero_kernel<<<1, 32>>>(out);

    // 148 SMs x 4 blocks = one full wave
    jsd_reduce_kernel<<<592, 256>>>(p4, q4, out, n4);
}

// round 9
// speedup vs baseline: 1.0926x; 1.0269x over previous
#include <cuda_runtime.h>
#include <cuda_bf16.h>

// HeadWise_JSD: out = (0.5/12) * sum p * (log p - log q)   [kl_pm == 0 exactly]
// Streaming reduction over 2 x 201 MB fp32.
// R8 (63.5us): light math (2 MUFU + 2 FMUL/elem) dropped alu 41->18%, issue
// 49->33%; DRAM flat at 76%. R9 tests the last untried interaction: light
// math x high warp count. 6 blocks/SM (888 blocks = one wave), 4-deep batch
// to fit the 42-reg budget -> 50% more independent load streams per SM.

static __device__ __forceinline__ float term(float p, float q) {
    // p * lg2(p/q): MUFU.RCP + FMUL + MUFU.LG2 + FMUL. abs err ~2^-22/op,
    // weighted by sum(p) vs output O(250) -> ~1e-5 worst case. Fine vs 1e-3.
    float r = __fdividef(p, q);
    return p * __log2f(r);
}

static __device__ __forceinline__ float term4(float4 pv, float4 qv) {
    float a = term(pv.x, qv.x) + term(pv.y, qv.y);
    float b = term(pv.z, qv.z) + term(pv.w, qv.w);
    return a + b;
}

__global__ void jsd_zero_kernel(float* out) {
    if (threadIdx.x == 0 && blockIdx.x == 0) out[0] = 0.0f;
}

__global__ __launch_bounds__(256, 6) void jsd_reduce_kernel(
    const float4* __restrict__ p4,
    const float4* __restrict__ q4,
    float* __restrict__ out,
    int n4)
{
    const int stride = gridDim.x * 256;
    int i = blockIdx.x * 256 + threadIdx.x;

    float a0 = 0.0f, a1 = 0.0f;

    // 4 front-batched streaming LDG.128.CS per macro-iter; MLP comes from
    // 48 warps/SM x 4 rather than per-thread depth.
    for (; i + stride < n4; i += 2 * stride) {
        float4 p0 = __ldcs(p4 + i);
        float4 p1 = __ldcs(p4 + i + stride);
        float4 q0 = __ldcs(q4 + i);
        float4 q1 = __ldcs(q4 + i + stride);
        a0 += term4(p0, q0);
        a1 += term4(p1, q1);
    }
    for (; i < n4; i += stride)
        a0 += term4(__ldcs(p4 + i), __ldcs(q4 + i));

    // log2-units -> nats
    float acc = (a0 + a1) * 0.69314718055994531f;

    #pragma unroll
    for (int o = 16; o; o >>= 1)
        acc += __shfl_xor_sync(0xffffffffu, acc, o);

    __shared__ float smem[8];
    int lane = threadIdx.x & 31;
    int warp = threadIdx.x >> 5;
    if (lane == 0) smem[warp] = acc;
    __syncthreads();

    if (warp == 0) {
        float v = (lane < 8) ? smem[lane] : 0.0f;
        #pragma unroll
        for (int o = 4; o; o >>= 1)
            v += __shfl_xor_sync(0xffffffffu, v, o);
        if (lane == 0)
            atomicAdd(out, v * (0.5f / 12.0f));
    }
}

extern "C" void kernel_launch(void* const* d_in, const int* in_sizes, int n_in,
                              void* d_out, int out_size) {
    const float4* p4 = (const float4*)d_in[0];
    const float4* q4 = (const float4*)d_in[1];
    float* out = (float*)d_out;

    int n  = in_sizes[0];     // 1024*12*4096
    int n4 = n >> 2;          // 12,582,912 float4 pairs

    jsd_zero_kernel<<<1, 32>>>(out);

    // 148 SMs x 6 blocks = 888 blocks: one full wave at 6 blocks/SM
    jsd_reduce_kernel<<<888, 256>>>(p4, q4, out, n4);
}